// round 8
// baseline (speedup 1.0000x reference)
#include <cuda_runtime.h>

#define P      16384
#define BM     128
#define NC     10
#define KSEL   819
#define NMASK  9830
#define NT     512
#define EQCAP  512

// scratch (no allocations allowed)
__device__ unsigned char g_block[BM * P];
__device__ int g_cidx[BM * NC];

// monotone uint transform for float ordering (handles tiny negative d2)
__device__ __forceinline__ unsigned int fkey(float f) {
    unsigned int u = __float_as_uint(f);
    return u ^ ((u >> 31) ? 0xFFFFFFFFu : 0x80000000u);
}

// warp-aggregated histogram increment (one atomic per distinct bucket per warp)
__device__ __forceinline__ void hist_add(int* hist, unsigned int bkt) {
    unsigned int m = __match_any_sync(__activemask(), bkt);
    int leader = __ffs(m) - 1;
    if ((int)(threadIdx.x & 31) == leader) atomicAdd(&hist[bkt], __popc(m));
}

// parallel bucket find: inclusive scan of 256 buckets, locate rank `remaining`.
// Outputs: *s_sb = bucket holding the rank, *s_cum = count strictly below it.
__device__ __forceinline__ void find_bucket(const int* hist, int remaining,
                                            int* s_scan, int* s_sb, int* s_cum) {
    int t = threadIdx.x;
    if (t < 256) s_scan[t] = hist[t];
    __syncthreads();
    #pragma unroll
    for (int off = 1; off < 256; off <<= 1) {
        int v = 0;
        if (t < 256 && t >= off) v = s_scan[t - off];
        __syncthreads();
        if (t < 256) s_scan[t] += v;
        __syncthreads();
    }
    if (t < 256) {
        int lo = t ? s_scan[t - 1] : 0;
        if (lo < remaining && remaining <= s_scan[t]) { *s_sb = t; *s_cum = lo; }
    }
    __syncthreads();
}

// Refine bytes 2..0 over the compacted candidate list (all share top byte).
// Returns final threshold T via prefix; updates *p_rem to ties-within-T count.
__device__ __forceinline__ unsigned int refine_candidates(
    const unsigned int* s_keys, const unsigned short* s_cand, int ncand,
    unsigned int prefix, int* p_rem, int* hist, int* s_scan, int* s_sb, int* s_cum) {
    int t = threadIdx.x;
    int remaining = *p_rem;
    for (int shift = 16; shift >= 0; shift -= 8) {
        find_bucket(hist, remaining, s_scan, s_sb, s_cum);
        unsigned int sb = (unsigned int)*s_sb;
        remaining -= *s_cum;
        prefix |= sb << shift;
        if (shift == 0) break;
        for (int i = t; i < 256; i += NT) hist[i] = 0;
        __syncthreads();
        for (int i = t; i < ncand; i += NT) {
            unsigned int k = s_keys[s_cand[i]];
            if ((k >> shift) == (prefix >> shift))
                hist_add(hist, (k >> (shift - 8)) & 255u);
        }
        __syncthreads();
    }
    *p_rem = remaining;
    return prefix;
}

// Kernel 1: zero block scratch; radix-select the 10 smallest rand_centers
// (set semantics — downstream union over centers is order-invariant).
__global__ void k_centers(const float* __restrict__ rc) {
    extern __shared__ unsigned int s_keys[];                 // P u32 (64KB)
    unsigned short* s_cand = (unsigned short*)(s_keys + P);  // P u16 (32KB)
    __shared__ int hist[256], s_scan[256];
    __shared__ int s_sb, s_cum, s_ncand, s_nsel, s_eqcnt;
    __shared__ int s_eq[EQCAP];
    int b = blockIdx.x, t = threadIdx.x;

    int4 z4 = make_int4(0, 0, 0, 0);
    int4* brow4 = (int4*)(g_block + (size_t)b * P);
    for (int i = t; i < P / 16; i += NT) brow4[i] = z4;
    for (int i = t; i < 256; i += NT) hist[i] = 0;
    if (t == 0) { s_ncand = 0; s_nsel = 0; s_eqcnt = 0; }
    __syncthreads();

    const float* row = rc + (size_t)b * P;
    for (int p = t; p < P; p += NT) {
        unsigned int k = __float_as_uint(row[p]);  // uniforms in [0,1): uint order == float order
        s_keys[p] = k;
        hist_add(hist, k >> 24);
    }
    __syncthreads();

    find_bucket(hist, NC, s_scan, &s_sb, &s_cum);
    unsigned int sb1 = (unsigned int)s_sb;
    int remaining = NC - s_cum;
    for (int i = t; i < 256; i += NT) hist[i] = 0;
    __syncthreads();

    int* cidx = g_cidx + b * NC;
    for (int p = t; p < P; p += NT) {
        unsigned int k = s_keys[p];
        unsigned int b3 = k >> 24;
        if (b3 < sb1) { int pos = atomicAdd(&s_nsel, 1); cidx[pos] = p; }
        else if (b3 == sb1) {
            int pos = atomicAdd(&s_ncand, 1);
            s_cand[pos] = (unsigned short)p;
            hist_add(hist, (k >> 16) & 255u);
        }
    }
    __syncthreads();

    int ncand = s_ncand;
    unsigned int T = refine_candidates(s_keys, s_cand, ncand, sb1 << 24,
                                       &remaining, hist, s_scan, &s_sb, &s_cum);

    for (int i = t; i < ncand; i += NT) {
        int p = s_cand[i];
        unsigned int k = s_keys[p];
        if (k < T) { int pos = atomicAdd(&s_nsel, 1); cidx[pos] = p; }
        else if (k == T) {
            int pos = atomicAdd(&s_eqcnt, 1);
            if (pos < EQCAP) s_eq[pos] = p;
        }
    }
    __syncthreads();
    int L = s_eqcnt;
    if (L <= EQCAP) {
        for (int i = t; i < L; i += NT) {
            int p = s_eq[i]; int rank = 0;
            for (int j = 0; j < L; j++) if (s_eq[j] < p) rank++;
            if (rank < remaining) { int pos = atomicAdd(&s_nsel, 1); cidx[pos] = p; }
        }
    } else {
        for (int i = t; i < ncand; i += NT) {
            int p = s_cand[i];
            if (s_keys[p] == T) {
                int rank = 0;
                for (int j = 0; j < ncand; j++) {
                    int q = s_cand[j];
                    if (s_keys[q] == T && q < p) rank++;
                }
                if (rank < remaining) { int pos = atomicAdd(&s_nsel, 1); cidx[pos] = p; }
            }
        }
    }
}

// Kernel 2: one block per (row, center). Eager-JAX fp32 d2:
//   norms un-fused (x*x+y*y)+z*z, dot = FMA chain, d2 = (ns+nc) - rn(2*dot).
// Fused sweep1 (compute+hist), sweep2 (mark+compact), refine on candidates.
__global__ void k_knn(const float* __restrict__ centers) {
    extern __shared__ unsigned int s_keys[];                 // P u32 (64KB)
    unsigned short* s_cand = (unsigned short*)(s_keys + P);  // P u16 (32KB)
    __shared__ int hist[256], s_scan[256];
    __shared__ int s_sb, s_cum, s_ncand, s_eqcnt;
    __shared__ int s_eq[EQCAP];
    int b = blockIdx.x / NC, c = blockIdx.x % NC;
    int t = threadIdx.x;

    const float* cen = centers + (size_t)(b >> 1) * P * 3;
    int ci = g_cidx[b * NC + c];
    float sx = cen[(size_t)ci * 3 + 0];
    float sy = cen[(size_t)ci * 3 + 1];
    float sz = cen[(size_t)ci * 3 + 2];
    float ns = __fadd_rn(__fadd_rn(__fmul_rn(sx, sx), __fmul_rn(sy, sy)), __fmul_rn(sz, sz));

    for (int i = t; i < 256; i += NT) hist[i] = 0;
    if (t == 0) { s_ncand = 0; s_eqcnt = 0; }
    __syncthreads();

    for (int p = t; p < P; p += NT) {
        float x = cen[(size_t)p * 3 + 0];
        float y = cen[(size_t)p * 3 + 1];
        float z = cen[(size_t)p * 3 + 2];
        float nc2 = __fadd_rn(__fadd_rn(__fmul_rn(x, x), __fmul_rn(y, y)), __fmul_rn(z, z));
        float dot = __fmaf_rn(sz, z, __fmaf_rn(sy, y, __fmul_rn(sx, x)));
        float d2 = __fsub_rn(__fadd_rn(ns, nc2), __fmul_rn(2.0f, dot));
        unsigned int k = fkey(d2);
        s_keys[p] = k;
        hist_add(hist, k >> 24);
    }
    __syncthreads();

    find_bucket(hist, KSEL, s_scan, &s_sb, &s_cum);
    unsigned int sb1 = (unsigned int)s_sb;
    int remaining = KSEL - s_cum;
    for (int i = t; i < 256; i += NT) hist[i] = 0;
    __syncthreads();

    unsigned char* brow = g_block + (size_t)b * P;
    for (int p = t; p < P; p += NT) {
        unsigned int k = s_keys[p];
        unsigned int b3 = k >> 24;
        if (b3 < sb1) brow[p] = 1;
        else if (b3 == sb1) {
            int pos = atomicAdd(&s_ncand, 1);
            s_cand[pos] = (unsigned short)p;
            hist_add(hist, (k >> 16) & 255u);
        }
    }
    __syncthreads();

    int ncand = s_ncand;
    unsigned int T = refine_candidates(s_keys, s_cand, ncand, sb1 << 24,
                                       &remaining, hist, s_scan, &s_sb, &s_cum);

    for (int i = t; i < ncand; i += NT) {
        int p = s_cand[i];
        unsigned int k = s_keys[p];
        if (k < T) brow[p] = 1;
        else if (k == T) {
            int pos = atomicAdd(&s_eqcnt, 1);
            if (pos < EQCAP) s_eq[pos] = p;
        }
    }
    __syncthreads();
    int L = s_eqcnt;
    if (L <= EQCAP) {
        for (int i = t; i < L; i += NT) {
            int p = s_eq[i]; int rank = 0;
            for (int j = 0; j < L; j++) if (s_eq[j] < p) rank++;
            if (rank < remaining) brow[p] = 1;
        }
    } else {
        for (int i = t; i < ncand; i += NT) {
            int p = s_cand[i];
            if (s_keys[p] == T) {
                int rank = 0;
                for (int j = 0; j < ncand; j++) {
                    int q = s_cand[j];
                    if (s_keys[q] == T && q < p) rank++;
                }
                if (rank < remaining) brow[p] = 1;
            }
        }
    }
}

// Kernel 3: per row, select (9830 - n_block) smallest rand_mask among
// non-block positions; write float32 mask (0.0/1.0).
__global__ void k_final(const float* __restrict__ rm, float* __restrict__ out) {
    extern __shared__ unsigned int s_keys[];                 // P u32 (64KB)
    unsigned short* s_cand = (unsigned short*)(s_keys + P);  // P u16 (32KB)
    __shared__ int hist[256], s_scan[256];
    __shared__ int s_sb, s_cum, s_ncand, s_eqcnt, s_nblk;
    __shared__ int s_eq[EQCAP];
    int b = blockIdx.x, t = threadIdx.x;

    for (int i = t; i < 256; i += NT) hist[i] = 0;
    if (t == 0) { s_ncand = 0; s_eqcnt = 0; s_nblk = 0; }
    __syncthreads();

    const unsigned char* brow = g_block + (size_t)b * P;
    const float* rrow = rm + (size_t)b * P;
    int local = 0;
    for (int p = t; p < P; p += NT) {
        unsigned char blk = brow[p];
        local += blk;
        unsigned int k = blk ? 0xFFFFFFFFu : __float_as_uint(rrow[p]);
        s_keys[p] = k;
        hist_add(hist, k >> 24);
    }
    // warp-reduce then one atomic per warp
    for (int off = 16; off; off >>= 1) local += __shfl_down_sync(0xFFFFFFFFu, local, off);
    if ((t & 31) == 0) atomicAdd(&s_nblk, local);
    __syncthreads();

    int rank = NMASK - s_nblk;   // >= 1640 (n_block <= 8190)
    find_bucket(hist, rank, s_scan, &s_sb, &s_cum);
    unsigned int sb1 = (unsigned int)s_sb;
    int remaining = rank - s_cum;
    for (int i = t; i < 256; i += NT) hist[i] = 0;
    __syncthreads();

    float* orow = out + (size_t)b * P;
    for (int p = t; p < P; p += NT) {
        unsigned int k = s_keys[p];
        unsigned int b3 = k >> 24;
        float v = 0.0f;
        if (k == 0xFFFFFFFFu) v = 1.0f;            // block position (always masked)
        else if (b3 < sb1) v = 1.0f;
        else if (b3 == sb1) {
            int pos = atomicAdd(&s_ncand, 1);
            s_cand[pos] = (unsigned short)p;
            hist_add(hist, (k >> 16) & 255u);
        }
        orow[p] = v;
    }
    __syncthreads();

    int ncand = s_ncand;
    unsigned int T = refine_candidates(s_keys, s_cand, ncand, sb1 << 24,
                                       &remaining, hist, s_scan, &s_sb, &s_cum);

    for (int i = t; i < ncand; i += NT) {
        int p = s_cand[i];
        unsigned int k = s_keys[p];
        if (k < T) orow[p] = 1.0f;
        else if (k == T) {
            int pos = atomicAdd(&s_eqcnt, 1);
            if (pos < EQCAP) s_eq[pos] = p;
        }
    }
    __syncthreads();
    int L = s_eqcnt;
    if (L <= EQCAP) {
        for (int i = t; i < L; i += NT) {
            int p = s_eq[i]; int rank2 = 0;
            for (int j = 0; j < L; j++) if (s_eq[j] < p) rank2++;
            if (rank2 < remaining) orow[p] = 1.0f;
        }
    } else {
        for (int i = t; i < ncand; i += NT) {
            int p = s_cand[i];
            if (s_keys[p] == T) {
                int rank2 = 0;
                for (int j = 0; j < ncand; j++) {
                    int q = s_cand[j];
                    if (s_keys[q] == T && q < p) rank2++;
                }
                if (rank2 < remaining) orow[p] = 1.0f;
            }
        }
    }
}

extern "C" void kernel_launch(void* const* d_in, const int* in_sizes, int n_in,
                              void* d_out, int out_size) {
    const float* centers = (const float*)d_in[0];  // [64, 16384, 3]
    const float* rc      = (const float*)d_in[1];  // [128, 16384]
    const float* rm      = (const float*)d_in[2];  // [128, 16384]
    float* out           = (float*)d_out;          // [128, 16384] float32 (bool->f32)

    const int SMEM = P * 4 + P * 2;   // keys (u32) + candidate indices (u16) = 96KB
    cudaFuncSetAttribute(k_centers, cudaFuncAttributeMaxDynamicSharedMemorySize, SMEM);
    cudaFuncSetAttribute(k_knn,     cudaFuncAttributeMaxDynamicSharedMemorySize, SMEM);
    cudaFuncSetAttribute(k_final,   cudaFuncAttributeMaxDynamicSharedMemorySize, SMEM);

    k_centers<<<BM, NT, SMEM>>>(rc);
    k_knn<<<BM * NC, NT, SMEM>>>(centers);
    k_final<<<BM, NT, SMEM>>>(rm, out);
}

// round 9
// speedup vs baseline: 2.7301x; 2.7301x over previous
#include <cuda_runtime.h>

#define P      16384
#define P4     (P / 4)
#define BM     128
#define NC     10
#define KSEL   819
#define NMASK  9830
#define NT     512
#define EQCAP  512

// scratch (no allocations allowed)
__device__ unsigned char g_block[BM * P];
__device__ int g_cidx[BM * NC];

// monotone uint transform for float ordering (handles tiny negative d2)
__device__ __forceinline__ unsigned int fkey(float f) {
    unsigned int u = __float_as_uint(f);
    return u ^ ((u >> 31) ? 0xFFFFFFFFu : 0x80000000u);
}

// warp-aggregated histogram increment (pass 1 only: heavy bucket concentration)
__device__ __forceinline__ void hist_add_agg(int* hist, unsigned int bkt) {
    unsigned int m = __match_any_sync(__activemask(), bkt);
    int leader = __ffs(m) - 1;
    if ((int)(threadIdx.x & 31) == leader) atomicAdd(&hist[bkt], __popc(m));
}

// Warp-0 scan of the 256-bucket histogram; locates the bucket holding rank
// `remaining`. Registers + shfl only: no block barriers inside.
__device__ __forceinline__ void find_bucket_warp(const int* hist, int remaining,
                                                 int* s_sb, int* s_cum) {
    int t = threadIdx.x;
    if (t < 32) {
        int v[8];
        int base = t * 8;
        #pragma unroll
        for (int j = 0; j < 8; j++) v[j] = hist[base + j];
        #pragma unroll
        for (int j = 1; j < 8; j++) v[j] += v[j - 1];   // lane-local inclusive
        int tot = v[7];
        int inc = tot;
        #pragma unroll
        for (int off = 1; off < 32; off <<= 1) {        // warp inclusive scan
            int n = __shfl_up_sync(0xFFFFFFFFu, inc, off);
            if (t >= off) inc += n;
        }
        int excl = inc - tot;
        if (excl < remaining && remaining <= inc) {     // exactly one lane
            int j = 7;
            #pragma unroll
            for (int jj = 6; jj >= 0; jj--)
                if (excl + v[jj] >= remaining) j = jj;
            *s_sb  = base + j;
            *s_cum = excl + (j ? v[j - 1] : 0);
        }
    }
}

// 4-pass radix rank-select over smem keys. Caller has already filled `keys`
// and built the byte-3 histogram in `hist` (pass 1 fused into the fill sweep).
// Returns threshold T; *p_ties = rank within the ==T group. Selected set =
// {k < T} + first *p_ties (by index) of {k == T}.
__device__ unsigned int radix_select_from_hist(const unsigned int* keys, int r,
                                               int* hist, int* s_sb, int* s_cum,
                                               int* p_ties) {
    int t = threadIdx.x;
    __syncthreads();                       // fill-sweep hist atomics complete
    find_bucket_warp(hist, r, s_sb, s_cum);
    __syncthreads();
    unsigned int prefix = ((unsigned int)*s_sb) << 24;
    int remaining = r - *s_cum;
    const uint4* k4 = (const uint4*)keys;
    for (int shift = 16; shift >= 0; shift -= 8) {
        if (t < 256) hist[t] = 0;
        __syncthreads();
        int psh = shift + 8;
        for (int i = t; i < P4; i += NT) {
            uint4 kk = k4[i];
            unsigned int ks[4] = {kk.x, kk.y, kk.z, kk.w};
            #pragma unroll
            for (int j = 0; j < 4; j++) {
                unsigned int k = ks[j];
                if ((k >> psh) == (prefix >> psh))
                    atomicAdd(&hist[(k >> shift) & 255u], 1);
            }
        }
        __syncthreads();
        find_bucket_warp(hist, remaining, s_sb, s_cum);
        __syncthreads();
        prefix |= ((unsigned int)*s_sb) << shift;
        remaining -= *s_cum;
    }
    *p_ties = remaining;
    return prefix;
}

// Kernel 1: zero block scratch; radix-select 10 smallest rand_centers
// (set semantics: downstream union over centers is order-invariant).
__global__ void k_centers(const float* __restrict__ rc) {
    extern __shared__ unsigned int s_keys[];   // P u32 (64KB)
    __shared__ int hist[256];
    __shared__ int s_sb, s_cum, s_nsel, s_eqcnt;
    __shared__ int s_eq[EQCAP];
    int b = blockIdx.x, t = threadIdx.x;

    int4 z4 = make_int4(0, 0, 0, 0);
    int4* brow4 = (int4*)(g_block + (size_t)b * P);
    for (int i = t; i < P / 16; i += NT) brow4[i] = z4;
    if (t < 256) hist[t] = 0;
    if (t == 0) { s_nsel = 0; s_eqcnt = 0; }
    __syncthreads();

    // uniforms in [0,1): raw uint order == float order
    const uint4* row4 = (const uint4*)(rc + (size_t)b * P);
    uint4* sk4 = (uint4*)s_keys;
    for (int i = t; i < P4; i += NT) {
        uint4 kk = row4[i];
        sk4[i] = kk;
        hist_add_agg(hist, kk.x >> 24);
        hist_add_agg(hist, kk.y >> 24);
        hist_add_agg(hist, kk.z >> 24);
        hist_add_agg(hist, kk.w >> 24);
    }

    int ties;
    unsigned int T = radix_select_from_hist(s_keys, NC, hist, &s_sb, &s_cum, &ties);

    int* cidx = g_cidx + b * NC;
    for (int p = t; p < P; p += NT) {
        unsigned int k = s_keys[p];
        if (k < T) { int pos = atomicAdd(&s_nsel, 1); cidx[pos] = p; }
        else if (k == T) {
            int pos = atomicAdd(&s_eqcnt, 1);
            if (pos < EQCAP) s_eq[pos] = p;
        }
    }
    __syncthreads();
    int L = s_eqcnt;
    if (L <= EQCAP) {
        for (int i = t; i < L; i += NT) {
            int p = s_eq[i]; int rank = 0;
            for (int j = 0; j < L; j++) if (s_eq[j] < p) rank++;
            if (rank < ties) { int pos = atomicAdd(&s_nsel, 1); cidx[pos] = p; }
        }
    } else {  // pathological tie explosion (still exact)
        for (int p = t; p < P; p += NT) {
            if (s_keys[p] == T) {
                int rank = 0;
                for (int j = 0; j < p; j++) if (s_keys[j] == T) rank++;
                if (rank < ties) { int pos = atomicAdd(&s_nsel, 1); cidx[pos] = p; }
            }
        }
    }
}

// Kernel 2: one block per (row, center). Eager-JAX fp32 d2:
//   norms un-fused (x*x+y*y)+z*z, dot = FMA chain, d2 = (ns+nc) - rn(2*dot).
__global__ void k_knn(const float* __restrict__ centers) {
    extern __shared__ unsigned int s_keys[];   // P u32 (64KB)
    __shared__ int hist[256];
    __shared__ int s_sb, s_cum, s_eqcnt;
    __shared__ int s_eq[EQCAP];
    int b = blockIdx.x / NC, c = blockIdx.x % NC;
    int t = threadIdx.x;

    const float* cen = centers + (size_t)(b >> 1) * P * 3;
    int ci = g_cidx[b * NC + c];
    float sx = cen[(size_t)ci * 3 + 0];
    float sy = cen[(size_t)ci * 3 + 1];
    float sz = cen[(size_t)ci * 3 + 2];
    float ns = __fadd_rn(__fadd_rn(__fmul_rn(sx, sx), __fmul_rn(sy, sy)), __fmul_rn(sz, sz));

    if (t < 256) hist[t] = 0;
    if (t == 0) s_eqcnt = 0;
    __syncthreads();

    for (int p = t; p < P; p += NT) {
        float x = cen[(size_t)p * 3 + 0];
        float y = cen[(size_t)p * 3 + 1];
        float z = cen[(size_t)p * 3 + 2];
        float nc2 = __fadd_rn(__fadd_rn(__fmul_rn(x, x), __fmul_rn(y, y)), __fmul_rn(z, z));
        float dot = __fmaf_rn(sz, z, __fmaf_rn(sy, y, __fmul_rn(sx, x)));
        float d2 = __fsub_rn(__fadd_rn(ns, nc2), __fmul_rn(2.0f, dot));
        unsigned int k = fkey(d2);
        s_keys[p] = k;
        hist_add_agg(hist, k >> 24);
    }

    int ties;
    unsigned int T = radix_select_from_hist(s_keys, KSEL, hist, &s_sb, &s_cum, &ties);

    unsigned char* brow = g_block + (size_t)b * P;
    const uint4* sk4 = (const uint4*)s_keys;
    for (int i = t; i < P4; i += NT) {
        uint4 kk = sk4[i];
        unsigned int ks[4] = {kk.x, kk.y, kk.z, kk.w};
        int p0 = i * 4;
        #pragma unroll
        for (int j = 0; j < 4; j++) {
            unsigned int k = ks[j];
            if (k < T) brow[p0 + j] = 1;
            else if (k == T) {
                int pos = atomicAdd(&s_eqcnt, 1);
                if (pos < EQCAP) s_eq[pos] = p0 + j;
            }
        }
    }
    __syncthreads();
    int L = s_eqcnt;
    if (L <= EQCAP) {
        for (int i = t; i < L; i += NT) {
            int p = s_eq[i]; int rank = 0;
            for (int j = 0; j < L; j++) if (s_eq[j] < p) rank++;
            if (rank < ties) brow[p] = 1;
        }
    } else {
        for (int p = t; p < P; p += NT) {
            if (s_keys[p] == T) {
                int rank = 0;
                for (int j = 0; j < p; j++) if (s_keys[j] == T) rank++;
                if (rank < ties) brow[p] = 1;
            }
        }
    }
}

// Kernel 3: per row, select (9830 - n_block) smallest rand_mask among
// non-block positions; write float32 mask (0.0/1.0).
__global__ void k_final(const float* __restrict__ rm, float* __restrict__ out) {
    extern __shared__ unsigned int s_keys[];   // P u32 (64KB)
    __shared__ int hist[256];
    __shared__ int s_sb, s_cum, s_eqcnt, s_nblk;
    __shared__ int s_eq[EQCAP];
    int b = blockIdx.x, t = threadIdx.x;

    if (t < 256) hist[t] = 0;
    if (t == 0) { s_eqcnt = 0; s_nblk = 0; }
    __syncthreads();

    const unsigned int* b4 = (const unsigned int*)(g_block + (size_t)b * P);
    const uint4* r4 = (const uint4*)(rm + (size_t)b * P);
    uint4* sk4 = (uint4*)s_keys;
    int local = 0;
    for (int i = t; i < P4; i += NT) {
        unsigned int blk4 = b4[i];     // 4 packed 0/1 bytes
        uint4 rr = r4[i];              // uniforms in [0,1): raw order OK
        local += __popc(blk4);
        uint4 kk;
        kk.x = (blk4 & 0x000000FFu) ? 0xFFFFFFFFu : rr.x;
        kk.y = (blk4 & 0x0000FF00u) ? 0xFFFFFFFFu : rr.y;
        kk.z = (blk4 & 0x00FF0000u) ? 0xFFFFFFFFu : rr.z;
        kk.w = (blk4 & 0xFF000000u) ? 0xFFFFFFFFu : rr.w;
        sk4[i] = kk;
        hist_add_agg(hist, kk.x >> 24);
        hist_add_agg(hist, kk.y >> 24);
        hist_add_agg(hist, kk.z >> 24);
        hist_add_agg(hist, kk.w >> 24);
    }
    for (int off = 16; off; off >>= 1) local += __shfl_down_sync(0xFFFFFFFFu, local, off);
    if ((t & 31) == 0) atomicAdd(&s_nblk, local);
    // radix_select_from_hist's leading __syncthreads() publishes s_nblk... but we
    // need the rank BEFORE calling it; sync here first.
    __syncthreads();
    int rank = NMASK - s_nblk;   // >= 1640 (n_block <= 8190); lands in non-block keys

    int ties;
    unsigned int T = radix_select_from_hist(s_keys, rank, hist, &s_sb, &s_cum, &ties);

    float* orow = out + (size_t)b * P;
    float4* o4 = (float4*)orow;
    const uint4* sk4c = (const uint4*)s_keys;
    for (int i = t; i < P4; i += NT) {
        uint4 kk = sk4c[i];
        unsigned int ks[4] = {kk.x, kk.y, kk.z, kk.w};
        float v[4];
        int p0 = i * 4;
        #pragma unroll
        for (int j = 0; j < 4; j++) {
            unsigned int k = ks[j];
            v[j] = (k == 0xFFFFFFFFu || k < T) ? 1.0f : 0.0f;
            if (k == T) {
                int pos = atomicAdd(&s_eqcnt, 1);
                if (pos < EQCAP) s_eq[pos] = p0 + j;
            }
        }
        o4[i] = make_float4(v[0], v[1], v[2], v[3]);
    }
    __syncthreads();
    int L = s_eqcnt;
    if (L <= EQCAP) {
        for (int i = t; i < L; i += NT) {
            int p = s_eq[i]; int rank2 = 0;
            for (int j = 0; j < L; j++) if (s_eq[j] < p) rank2++;
            if (rank2 < ties) orow[p] = 1.0f;
        }
    } else {
        for (int p = t; p < P; p += NT) {
            if (s_keys[p] == T) {
                int rank2 = 0;
                for (int j = 0; j < p; j++) if (s_keys[j] == T) rank2++;
                if (rank2 < ties) orow[p] = 1.0f;
            }
        }
    }
}

extern "C" void kernel_launch(void* const* d_in, const int* in_sizes, int n_in,
                              void* d_out, int out_size) {
    const float* centers = (const float*)d_in[0];  // [64, 16384, 3]
    const float* rc      = (const float*)d_in[1];  // [128, 16384]
    const float* rm      = (const float*)d_in[2];  // [128, 16384]
    float* out           = (float*)d_out;          // [128, 16384] float32 (bool->f32)

    const int SMEM = P * 4;   // 64KB keys
    cudaFuncSetAttribute(k_centers, cudaFuncAttributeMaxDynamicSharedMemorySize, SMEM);
    cudaFuncSetAttribute(k_knn,     cudaFuncAttributeMaxDynamicSharedMemorySize, SMEM);
    cudaFuncSetAttribute(k_final,   cudaFuncAttributeMaxDynamicSharedMemorySize, SMEM);

    k_centers<<<BM, NT, SMEM>>>(rc);
    k_knn<<<BM * NC, NT, SMEM>>>(centers);
    k_final<<<BM, NT, SMEM>>>(rm, out);
}

// round 11
// speedup vs baseline: 3.0231x; 1.1073x over previous
#include <cuda_runtime.h>

#define P      16384
#define P4     (P / 4)
#define BM     128
#define NC     10
#define KSEL   819
#define NMASK  9830
#define NT     512
#define EQCAP  512
#define CCAP   1024

// scratch (no allocations allowed)
__device__ unsigned char g_block[BM * P];
__device__ int g_cidx[BM * NC];

// monotone uint transform for float ordering (handles tiny negative d2)
__device__ __forceinline__ unsigned int fkey(float f) {
    unsigned int u = __float_as_uint(f);
    return u ^ ((u >> 31) ? 0xFFFFFFFFu : 0x80000000u);
}

// warp-aggregated histogram increment (pass 1 only: heavy bucket concentration)
__device__ __forceinline__ void hist_add_agg(int* hist, unsigned int bkt) {
    unsigned int m = __match_any_sync(__activemask(), bkt);
    int leader = __ffs(m) - 1;
    if ((int)(threadIdx.x & 31) == leader) atomicAdd(&hist[bkt], __popc(m));
}

// Warp-0 scan of the 256-bucket histogram; locates the bucket holding rank
// `remaining`. Registers + shfl only: no block barriers inside.
__device__ __forceinline__ void find_bucket_warp(const int* hist, int remaining,
                                                 int* s_sb, int* s_cum) {
    int t = threadIdx.x;
    if (t < 32) {
        int v[8];
        int base = t * 8;
        #pragma unroll
        for (int j = 0; j < 8; j++) v[j] = hist[base + j];
        #pragma unroll
        for (int j = 1; j < 8; j++) v[j] += v[j - 1];   // lane-local inclusive
        int tot = v[7];
        int inc = tot;
        #pragma unroll
        for (int off = 1; off < 32; off <<= 1) {        // warp inclusive scan
            int n = __shfl_up_sync(0xFFFFFFFFu, inc, off);
            if (t >= off) inc += n;
        }
        int excl = inc - tot;
        if (excl < remaining && remaining <= inc) {     // exactly one lane
            int j = 7;
            #pragma unroll
            for (int jj = 6; jj >= 0; jj--)
                if (excl + v[jj] >= remaining) j = jj;
            *s_sb  = base + j;
            *s_cum = excl + (j ? v[j - 1] : 0);
        }
    }
}

// 4-pass radix rank-select over smem keys (byte-3 hist pre-built by caller).
__device__ unsigned int radix_select_from_hist(const unsigned int* keys, int r,
                                               int* hist, int* s_sb, int* s_cum,
                                               int* p_ties) {
    int t = threadIdx.x;
    __syncthreads();                       // fill-sweep hist atomics complete
    find_bucket_warp(hist, r, s_sb, s_cum);
    __syncthreads();
    unsigned int prefix = ((unsigned int)*s_sb) << 24;
    int remaining = r - *s_cum;
    const uint4* k4 = (const uint4*)keys;
    for (int shift = 16; shift >= 0; shift -= 8) {
        if (t < 256) hist[t] = 0;
        __syncthreads();
        int psh = shift + 8;
        for (int i = t; i < P4; i += NT) {
            uint4 kk = k4[i];
            unsigned int ks[4] = {kk.x, kk.y, kk.z, kk.w};
            #pragma unroll
            for (int j = 0; j < 4; j++) {
                unsigned int k = ks[j];
                if ((k >> psh) == (prefix >> psh))
                    atomicAdd(&hist[(k >> shift) & 255u], 1);
            }
        }
        __syncthreads();
        find_bucket_warp(hist, remaining, s_sb, s_cum);
        __syncthreads();
        prefix |= ((unsigned int)*s_sb) << shift;
        remaining -= *s_cum;
    }
    *p_ties = remaining;
    return prefix;
}

// Kernel 1: zero block scratch; select the 10 smallest rand_centers by
// threshold-filter (+ uint-bisection + exact-tie fallback). Uniform [0,1)
// keys: raw uint order == float order. Set semantics (union downstream).
__global__ void k_centers(const float* __restrict__ rc) {
    __shared__ unsigned long long s_cand[CCAP];
    __shared__ int s_cnt, s_nsel;
    __shared__ unsigned long long s_min;
    int b = blockIdx.x, t = threadIdx.x;

    int4 z4 = make_int4(0, 0, 0, 0);
    int4* brow4 = (int4*)(g_block + (size_t)b * P);
    for (int i = t; i < P / 16; i += NT) brow4[i] = z4;

    const uint4* row4 = (const uint4*)(rc + (size_t)b * P);
    unsigned int thresh = 0x3B800000u;           // 2^-8: E[count]=64
    unsigned int lo = 0, hi = 0x3F800000u;       // 1.0f
    int cnt = 0, iter = 0;
    bool degenerate = false;
    while (true) {
        if (t == 0) s_cnt = 0;
        __syncthreads();
        for (int i = t; i < P4; i += NT) {
            uint4 kk = row4[i];
            unsigned int ks[4] = {kk.x, kk.y, kk.z, kk.w};
            #pragma unroll
            for (int j = 0; j < 4; j++) {
                if (ks[j] < thresh) {
                    int pos = atomicAdd(&s_cnt, 1);
                    if (pos < CCAP)
                        s_cand[pos] = ((unsigned long long)ks[j] << 32) | (unsigned int)(i * 4 + j);
                }
            }
        }
        __syncthreads();
        cnt = s_cnt;
        if (cnt >= NC && cnt <= CCAP) break;
        if (cnt < NC) lo = thresh; else hi = thresh;
        if (hi - lo <= 1 || ++iter > 40) { degenerate = true; break; }
        thresh = lo + ((hi - lo) >> 1);
        __syncthreads();
    }

    int* cidx = g_cidx + b * NC;
    if (!degenerate) {
        if (t == 0) s_nsel = 0;
        __syncthreads();
        for (int i = t; i < cnt; i += NT) {
            unsigned long long me = s_cand[i];
            int rank = 0;
            for (int j = 0; j < cnt; j++) rank += (s_cand[j] < me);
            if (rank < NC) { int pos = atomicAdd(&s_nsel, 1); cidx[pos] = (int)(me & 0xFFFFFFFFull); }
        }
    } else {
        // Massive tie group straddles [NC, CCAP]: exact iterative selection.
        unsigned long long low = 0;
        for (int i = 0; i < NC; i++) {
            if (t == 0) s_min = ~0ull;
            __syncthreads();
            unsigned long long local = ~0ull;
            for (int p = t; p < P; p += NT) {
                unsigned long long key =
                    ((unsigned long long)__float_as_uint(rc[(size_t)b * P + p]) << 32) | (unsigned int)p;
                if (key >= low && key < local) local = key;
            }
            atomicMin(&s_min, local);
            __syncthreads();
            if (t == 0) cidx[i] = (int)(s_min & 0xFFFFFFFFull);
            low = s_min + 1;
            __syncthreads();
        }
    }
}

// Kernel 2: one block per (row, center). Eager-JAX fp32 d2:
//   norms un-fused (x*x+y*y)+z*z, dot = FMA chain, d2 = (ns+nc) - rn(2*dot).
// Fill sweep uses 3x uint4 loads per 4 points (4x fewer LDG instructions).
__global__ void k_knn(const float* __restrict__ centers) {
    extern __shared__ unsigned int s_keys[];   // P u32 (64KB)
    __shared__ int hist[256];
    __shared__ int s_sb, s_cum, s_eqcnt;
    __shared__ int s_eq[EQCAP];
    int b = blockIdx.x / NC, c = blockIdx.x % NC;
    int t = threadIdx.x;

    const float* cen = centers + (size_t)(b >> 1) * P * 3;
    int ci = g_cidx[b * NC + c];
    float sx = cen[(size_t)ci * 3 + 0];
    float sy = cen[(size_t)ci * 3 + 1];
    float sz = cen[(size_t)ci * 3 + 2];
    float ns = __fadd_rn(__fadd_rn(__fmul_rn(sx, sx), __fmul_rn(sy, sy)), __fmul_rn(sz, sz));

    if (t < 256) hist[t] = 0;
    if (t == 0) s_eqcnt = 0;
    __syncthreads();

    const uint4* c4 = (const uint4*)cen;
    uint4* sk4 = (uint4*)s_keys;
    for (int g = t; g < P4; g += NT) {
        uint4 u0 = c4[g * 3 + 0];
        uint4 u1 = c4[g * 3 + 1];
        uint4 u2 = c4[g * 3 + 2];
        float xs[4] = {__uint_as_float(u0.x), __uint_as_float(u0.w),
                       __uint_as_float(u1.z), __uint_as_float(u2.y)};
        float ys[4] = {__uint_as_float(u0.y), __uint_as_float(u1.x),
                       __uint_as_float(u1.w), __uint_as_float(u2.z)};
        float zs[4] = {__uint_as_float(u0.z), __uint_as_float(u1.y),
                       __uint_as_float(u2.x), __uint_as_float(u2.w)};
        unsigned int kout[4];
        #pragma unroll
        for (int j = 0; j < 4; j++) {
            float x = xs[j], y = ys[j], z = zs[j];
            float nc2 = __fadd_rn(__fadd_rn(__fmul_rn(x, x), __fmul_rn(y, y)), __fmul_rn(z, z));
            float dot = __fmaf_rn(sz, z, __fmaf_rn(sy, y, __fmul_rn(sx, x)));
            float d2 = __fsub_rn(__fadd_rn(ns, nc2), __fmul_rn(2.0f, dot));
            kout[j] = fkey(d2);
        }
        sk4[g] = make_uint4(kout[0], kout[1], kout[2], kout[3]);
        #pragma unroll
        for (int j = 0; j < 4; j++) hist_add_agg(hist, kout[j] >> 24);
    }

    int ties;
    unsigned int T = radix_select_from_hist(s_keys, KSEL, hist, &s_sb, &s_cum, &ties);

    unsigned char* brow = g_block + (size_t)b * P;
    const uint4* sk4c = (const uint4*)s_keys;
    for (int i = t; i < P4; i += NT) {
        uint4 kk = sk4c[i];
        unsigned int ks[4] = {kk.x, kk.y, kk.z, kk.w};
        int p0 = i * 4;
        #pragma unroll
        for (int j = 0; j < 4; j++) {
            unsigned int k = ks[j];
            if (k < T) brow[p0 + j] = 1;
            else if (k == T) {
                int pos = atomicAdd(&s_eqcnt, 1);
                if (pos < EQCAP) s_eq[pos] = p0 + j;
            }
        }
    }
    __syncthreads();
    int L = s_eqcnt;
    if (L <= EQCAP) {
        for (int i = t; i < L; i += NT) {
            int p = s_eq[i]; int rank = 0;
            for (int j = 0; j < L; j++) if (s_eq[j] < p) rank++;
            if (rank < ties) brow[p] = 1;
        }
    } else {
        for (int p = t; p < P; p += NT) {
            if (s_keys[p] == T) {
                int rank = 0;
                for (int j = 0; j < p; j++) if (s_keys[j] == T) rank++;
                if (rank < ties) brow[p] = 1;
            }
        }
    }
}

// Kernel 3: per row, select (9830 - n_block) smallest rand_mask among
// non-block positions; write float32 mask (0.0/1.0).
__global__ void k_final(const float* __restrict__ rm, float* __restrict__ out) {
    extern __shared__ unsigned int s_keys[];   // P u32 (64KB)
    __shared__ int hist[256];
    __shared__ int s_sb, s_cum, s_eqcnt, s_nblk;
    __shared__ int s_eq[EQCAP];
    int b = blockIdx.x, t = threadIdx.x;

    if (t < 256) hist[t] = 0;
    if (t == 0) { s_eqcnt = 0; s_nblk = 0; }
    __syncthreads();

    const unsigned int* b4 = (const unsigned int*)(g_block + (size_t)b * P);
    const uint4* r4 = (const uint4*)(rm + (size_t)b * P);
    uint4* sk4 = (uint4*)s_keys;
    int local = 0;
    for (int i = t; i < P4; i += NT) {
        unsigned int blk4 = b4[i];     // 4 packed 0/1 bytes
        uint4 rr = r4[i];              // uniforms in [0,1): raw order OK
        local += __popc(blk4);
        uint4 kk;
        kk.x = (blk4 & 0x000000FFu) ? 0xFFFFFFFFu : rr.x;
        kk.y = (blk4 & 0x0000FF00u) ? 0xFFFFFFFFu : rr.y;
        kk.z = (blk4 & 0x00FF0000u) ? 0xFFFFFFFFu : rr.z;
        kk.w = (blk4 & 0xFF000000u) ? 0xFFFFFFFFu : rr.w;
        sk4[i] = kk;
        hist_add_agg(hist, kk.x >> 24);
        hist_add_agg(hist, kk.y >> 24);
        hist_add_agg(hist, kk.z >> 24);
        hist_add_agg(hist, kk.w >> 24);
    }
    for (int off = 16; off; off >>= 1) local += __shfl_down_sync(0xFFFFFFFFu, local, off);
    if ((t & 31) == 0) atomicAdd(&s_nblk, local);
    __syncthreads();
    int rank = NMASK - s_nblk;   // >= 1640 (n_block <= 8190); lands in non-block keys

    int ties;
    unsigned int T = radix_select_from_hist(s_keys, rank, hist, &s_sb, &s_cum, &ties);

    float* orow = out + (size_t)b * P;
    float4* o4 = (float4*)orow;
    const uint4* sk4c = (const uint4*)s_keys;
    for (int i = t; i < P4; i += NT) {
        uint4 kk = sk4c[i];
        unsigned int ks[4] = {kk.x, kk.y, kk.z, kk.w};
        float v[4];
        int p0 = i * 4;
        #pragma unroll
        for (int j = 0; j < 4; j++) {
            unsigned int k = ks[j];
            v[j] = (k == 0xFFFFFFFFu || k < T) ? 1.0f : 0.0f;
            if (k == T) {
                int pos = atomicAdd(&s_eqcnt, 1);
                if (pos < EQCAP) s_eq[pos] = p0 + j;
            }
        }
        o4[i] = make_float4(v[0], v[1], v[2], v[3]);
    }
    __syncthreads();
    int L = s_eqcnt;
    if (L <= EQCAP) {
        for (int i = t; i < L; i += NT) {
            int p = s_eq[i]; int rank2 = 0;
            for (int j = 0; j < L; j++) if (s_eq[j] < p) rank2++;
            if (rank2 < ties) orow[p] = 1.0f;
        }
    } else {
        for (int p = t; p < P; p += NT) {
            if (s_keys[p] == T) {
                int rank2 = 0;
                for (int j = 0; j < p; j++) if (s_keys[j] == T) rank2++;
                if (rank2 < ties) orow[p] = 1.0f;
            }
        }
    }
}

extern "C" void kernel_launch(void* const* d_in, const int* in_sizes, int n_in,
                              void* d_out, int out_size) {
    const float* centers = (const float*)d_in[0];  // [64, 16384, 3]
    const float* rc      = (const float*)d_in[1];  // [128, 16384]
    const float* rm      = (const float*)d_in[2];  // [128, 16384]
    float* out           = (float*)d_out;          // [128, 16384] float32 (bool->f32)

    const int SMEM = P * 4;   // 64KB keys
    cudaFuncSetAttribute(k_knn,   cudaFuncAttributeMaxDynamicSharedMemorySize, SMEM);
    cudaFuncSetAttribute(k_final, cudaFuncAttributeMaxDynamicSharedMemorySize, SMEM);

    k_centers<<<BM, NT>>>(rc);
    k_knn<<<BM * NC, NT, SMEM>>>(centers);
    k_final<<<BM, NT, SMEM>>>(rm, out);
}